// round 1
// baseline (speedup 1.0000x reference)
#include <cuda_runtime.h>

// Problem constants (fixed shapes for this problem)
#define Bdim 2
#define Sdim 512
#define Fdim 16384
#define Ddim 768
#define Mdim 262144
#define BS   (Bdim * Sdim)       // 1024
#define D4   (Ddim / 4)          // 192 float4 per encoder/decoder row
#define C4   (BS / 4)            // 256 float4 per column-panel row

// -------- device scratch (static, no allocation) --------
__device__ float4 g_Ut[(size_t)Fdim * D4];   // up_decoder^T  [F, 768]   48 MB
__device__ float4 g_Xt[(size_t)Fdim * C4];   // up_facts^T    [F, 1024]  64 MB
__device__ float4 g_outT[(size_t)Fdim * C4]; // out^T         [F, 1024]  64 MB
__device__ float  g_vals[Mdim];
__device__ int    g_ii[Mdim];
__device__ int    g_jj[Mdim];
__device__ int    g_rowptr[Fdim + 1];
__device__ int    g_is64;

// -------- dtype detection: int64 vs int32 indices --------
// i_indices is sorted ascending in [0, F). At int64-index 65536 (byte offset
// 512KB, in-bounds whether the buffer is 1MB int32 or 2MB int64):
//   - true int64: value = i[65536] in [0, F)
//   - actually int32: value = i32[131072] | (i32[131073] << 32)  ->  >= 2^32
__global__ void k_detect(const long long* __restrict__ ip) {
    long long v = ip[65536];
    g_is64 = (v >= 0 && v < (long long)Fdim) ? 1 : 0;
}

__global__ void k_convert(const void* __restrict__ ip, const void* __restrict__ jp) {
    int m = blockIdx.x * blockDim.x + threadIdx.x;
    if (m >= Mdim) return;
    if (g_is64) {
        g_ii[m] = (int)((const long long*)ip)[m];
        g_jj[m] = (int)((const long long*)jp)[m];
    } else {
        g_ii[m] = ((const int*)ip)[m];
        g_jj[m] = ((const int*)jp)[m];
    }
}

// -------- CSR row pointers via binary search on sorted i --------
__global__ void k_rowptr() {
    int r = blockIdx.x * blockDim.x + threadIdx.x;
    if (r > Fdim) return;
    int lo = 0, hi = Mdim;
    while (lo < hi) {
        int mid = (lo + hi) >> 1;
        if (g_ii[mid] < r) lo = mid + 1; else hi = mid;
    }
    g_rowptr[r] = lo;
}

// -------- tiled transpose (rows, cols both multiples of 32) --------
__device__ __forceinline__ void transpose_body(const float* __restrict__ src,
                                               float* __restrict__ dst,
                                               int rows, int cols) {
    __shared__ float tile[32][33];
    int bx = blockIdx.x * 32, by = blockIdx.y * 32;
    int tx = threadIdx.x, ty0 = threadIdx.y;
#pragma unroll
    for (int ty = ty0; ty < 32; ty += 8)
        tile[ty][tx] = src[(size_t)(by + ty) * cols + (bx + tx)];
    __syncthreads();
#pragma unroll
    for (int ty = ty0; ty < 32; ty += 8)
        dst[(size_t)(bx + ty) * rows + (by + tx)] = tile[tx][ty];
}

__global__ void k_transU(const float* __restrict__ s) { transpose_body(s, (float*)g_Ut, Ddim, Fdim); }
__global__ void k_transX(const float* __restrict__ s) { transpose_body(s, (float*)g_Xt, BS,   Fdim); }
__global__ void k_transO(float* __restrict__ d)       { transpose_body((const float*)g_outT, d, Fdim, BS); }

// -------- values[m] = <down_encoder[i], up_decoder^T[j]>  (one warp per m) --------
__global__ void k_values(const float* __restrict__ Dn) {
    int gw   = (blockIdx.x * blockDim.x + threadIdx.x) >> 5;
    int lane = threadIdx.x & 31;
    if (gw >= Mdim) return;
    int i = g_ii[gw], j = g_jj[gw];
    const float4* __restrict__ Dr = (const float4*)Dn + (size_t)i * D4;
    const float4* __restrict__ Ur = g_Ut + (size_t)j * D4;
    float s = 0.f;
#pragma unroll
    for (int k = 0; k < 6; k++) {
        float4 a = Dr[k * 32 + lane];
        float4 b = Ur[k * 32 + lane];
        s += a.x * b.x + a.y * b.y + a.z * b.z + a.w * b.w;
    }
#pragma unroll
    for (int o = 16; o > 0; o >>= 1) s += __shfl_xor_sync(0xffffffffu, s, o);
    if (lane == 0) g_vals[gw] = s;
}

// -------- SpMM: outT[r, :] = sum_{m in row r} vals[m] * Xt[j_m, :] --------
// 256 threads own the full 1024-column panel (float4 each). Indices/values are
// read once per nnz (broadcast), X row read is a perfectly coalesced 4KB burst.
#define SPMM_ROWS 16
__global__ void k_spmm() {
    int t  = threadIdx.x;              // 0..255 -> float4 column
    int r0 = blockIdx.x * SPMM_ROWS;
#pragma unroll 1
    for (int rr = 0; rr < SPMM_ROWS; rr++) {
        int r  = r0 + rr;
        int mb = g_rowptr[r], me = g_rowptr[r + 1];
        float4 acc = make_float4(0.f, 0.f, 0.f, 0.f);
        int m = mb;
        if (m < me) {
            int    j = g_jj[m];
            float  v = g_vals[m];
            float4 x = g_Xt[(size_t)j * C4 + t];
            for (++m; m < me; ++m) {
                int    jn = g_jj[m];
                float  vn = g_vals[m];
                float4 xn = g_Xt[(size_t)jn * C4 + t];
                acc.x += v * x.x; acc.y += v * x.y;
                acc.z += v * x.z; acc.w += v * x.w;
                v = vn; x = xn;
            }
            acc.x += v * x.x; acc.y += v * x.y;
            acc.z += v * x.z; acc.w += v * x.w;
        }
        g_outT[(size_t)r * C4 + t] = acc;
    }
}

extern "C" void kernel_launch(void* const* d_in, const int* in_sizes, int n_in,
                              void* d_out, int out_size) {
    const float* up_facts = (const float*)d_in[0];   // [B, S, F] fp32
    const float* down_enc = (const float*)d_in[1];   // [F, D]    fp32
    const float* up_dec   = (const float*)d_in[2];   // [D, F]    fp32
    const void*  iI       = d_in[3];                 // [M] int64 (or int32)
    const void*  jI       = d_in[4];                 // [M] int64 (or int32)
    float*       out      = (float*)d_out;           // [B, S, F] fp32

    dim3 tb(32, 8);

    k_detect<<<1, 1>>>((const long long*)iI);
    k_convert<<<Mdim / 256, 256>>>(iI, jI);

    k_transU<<<dim3(Fdim / 32, Ddim / 32), tb>>>(up_dec);   // U^T  [F, 768]
    k_transX<<<dim3(Fdim / 32, BS / 32),   tb>>>(up_facts); // X^T  [F, 1024]

    k_rowptr<<<(Fdim + 256) / 256, 256>>>();

    k_values<<<(Mdim * 32) / 256, 256>>>(down_enc);

    k_spmm<<<Fdim / SPMM_ROWS, 256>>>();

    k_transO<<<dim3(BS / 32, Fdim / 32), tb>>>(out);        // out [1024, F]
}

// round 2
// speedup vs baseline: 1.1243x; 1.1243x over previous
#include <cuda_runtime.h>
#include <cuda_fp16.h>

#define Bdim 2
#define Sdim 512
#define Fdim 16384
#define Ddim 768
#define Mdim 262144
#define BS   (Bdim * Sdim)       // 1024
#define D4   (Ddim / 4)          // 192 float4 per encoder/decoder row

// -------- device scratch (static, no allocation) --------
__device__ float4 g_Ut[(size_t)Fdim * D4];      // up_decoder^T [F, 768] fp32, 48 MB
__device__ uint2  g_Xh[(size_t)Fdim * 256];     // up_facts^T   [F,1024] fp16, 32 MB
__device__ float  g_vals[Mdim];
__device__ int    g_ii[Mdim];
__device__ int    g_jj[Mdim];
__device__ int    g_rowptr[Fdim + 1];
__device__ int    g_is64;

// -------- dtype detection: int64 vs int32 indices --------
__global__ void k_detect(const long long* __restrict__ ip) {
    long long v = ip[65536];
    g_is64 = (v >= 0 && v < (long long)Fdim) ? 1 : 0;
}

__global__ void k_convert(const void* __restrict__ ip, const void* __restrict__ jp) {
    int m = blockIdx.x * blockDim.x + threadIdx.x;
    if (m >= Mdim) return;
    if (g_is64) {
        g_ii[m] = (int)((const long long*)ip)[m];
        g_jj[m] = (int)((const long long*)jp)[m];
    } else {
        g_ii[m] = ((const int*)ip)[m];
        g_jj[m] = ((const int*)jp)[m];
    }
}

// -------- CSR row pointers via binary search on sorted i --------
__global__ void k_rowptr() {
    int r = blockIdx.x * blockDim.x + threadIdx.x;
    if (r > Fdim) return;
    int lo = 0, hi = Mdim;
    while (lo < hi) {
        int mid = (lo + hi) >> 1;
        if (g_ii[mid] < r) lo = mid + 1; else hi = mid;
    }
    g_rowptr[r] = lo;
}

// -------- transpose U (fp32 -> fp32), 32x32 scalar tiles --------
__global__ void k_transU(const float* __restrict__ src) {
    __shared__ float tile[32][33];
    int bx = blockIdx.x * 32, by = blockIdx.y * 32;
    int tx = threadIdx.x, ty0 = threadIdx.y;
#pragma unroll
    for (int ty = ty0; ty < 32; ty += 8)
        tile[ty][tx] = src[(size_t)(by + ty) * Fdim + (bx + tx)];
    __syncthreads();
    float* dst = (float*)g_Ut;
#pragma unroll
    for (int ty = ty0; ty < 32; ty += 8)
        dst[(size_t)(bx + ty) * Ddim + (by + tx)] = tile[tx][ty];
}

// -------- transpose X (fp32 -> fp16), 32x32 scalar tiles --------
__global__ void k_transX(const float* __restrict__ src) {
    __shared__ float tile[32][33];
    int bx = blockIdx.x * 32, by = blockIdx.y * 32;
    int tx = threadIdx.x, ty0 = threadIdx.y;
#pragma unroll
    for (int ty = ty0; ty < 32; ty += 8)
        tile[ty][tx] = src[(size_t)(by + ty) * Fdim + (bx + tx)];
    __syncthreads();
    __half* dst = (__half*)g_Xh;
#pragma unroll
    for (int ty = ty0; ty < 32; ty += 8)
        dst[(size_t)(bx + ty) * BS + (by + tx)] = __float2half(tile[tx][ty]);
}

// -------- values[m] = <down_encoder[i], up_decoder^T[j]>, one warp per m --------
__global__ void k_values(const float* __restrict__ Dn) {
    int gw   = (blockIdx.x * blockDim.x + threadIdx.x) >> 5;
    int lane = threadIdx.x & 31;
    if (gw >= Mdim) return;
    int i = g_ii[gw], j = g_jj[gw];
    const float4* __restrict__ Dr = (const float4*)Dn + (size_t)i * D4;
    const float4* __restrict__ Ur = g_Ut + (size_t)j * D4;
    float s = 0.f;
#pragma unroll
    for (int k = 0; k < 6; k++) {
        float4 a = Dr[k * 32 + lane];
        float4 b = Ur[k * 32 + lane];
        s += a.x * b.x + a.y * b.y + a.z * b.z + a.w * b.w;
    }
#pragma unroll
    for (int o = 16; o > 0; o >>= 1) s += __shfl_xor_sync(0xffffffffu, s, o);
    if (lane == 0) g_vals[gw] = s;
}

// -------- fused SpMM + output transpose --------
// Block owns 8 rows x 1024-col panel. Thread t accumulates bs columns 4t..4t+3
// (float4) per row, reading Xh rows as coalesced 2KB bursts (uint2/thread).
// Epilogue stages via smem [8][1028] (pad 4 floats => STS.128 and the
// transposed LDS are both bank-conflict-free), then writes `out` bs-major in
// 32B sector-aligned chunks.
#define SR 8
__global__ void __launch_bounds__(256) k_spmm(float* __restrict__ out) {
    __shared__ float stage[SR][1028];
    int t  = threadIdx.x;
    int r0 = blockIdx.x * SR;

    float4 acc[SR];
#pragma unroll
    for (int rr = 0; rr < SR; rr++) {
        int r  = r0 + rr;
        int m  = g_rowptr[r], me = g_rowptr[r + 1];
        float4 a = make_float4(0.f, 0.f, 0.f, 0.f);
        if (m < me) {
            int   j = g_jj[m];
            float v = g_vals[m];
            uint2 x = g_Xh[(size_t)j * 256 + t];
            for (++m; m < me; ++m) {
                int   jn = g_jj[m];
                float vn = g_vals[m];
                uint2 xn = g_Xh[(size_t)jn * 256 + t];
                float2 lo = __half22float2(*(const __half2*)&x.x);
                float2 hi = __half22float2(*(const __half2*)&x.y);
                a.x += v * lo.x; a.y += v * lo.y;
                a.z += v * hi.x; a.w += v * hi.y;
                v = vn; x = xn;
            }
            float2 lo = __half22float2(*(const __half2*)&x.x);
            float2 hi = __half22float2(*(const __half2*)&x.y);
            a.x += v * lo.x; a.y += v * lo.y;
            a.z += v * hi.x; a.w += v * hi.y;
        }
        acc[rr] = a;
    }

#pragma unroll
    for (int rr = 0; rr < SR; rr++)
        *(float4*)&stage[rr][4 * t] = acc[rr];
    __syncthreads();

#pragma unroll
    for (int it = 0; it < 8; it++) {
        int g  = it * 256 + t;
        int c  = g & 1;        // which float4 of the 8-row group
        int bs = g >> 1;       // 0..1023
        float4 o;
        o.x = stage[4 * c + 0][bs];
        o.y = stage[4 * c + 1][bs];
        o.z = stage[4 * c + 2][bs];
        o.w = stage[4 * c + 3][bs];
        *(float4*)&out[(size_t)bs * Fdim + r0 + 4 * c] = o;
    }
}

extern "C" void kernel_launch(void* const* d_in, const int* in_sizes, int n_in,
                              void* d_out, int out_size) {
    const float* up_facts = (const float*)d_in[0];   // [B, S, F] fp32
    const float* down_enc = (const float*)d_in[1];   // [F, D]    fp32
    const float* up_dec   = (const float*)d_in[2];   // [D, F]    fp32
    const void*  iI       = d_in[3];                 // [M] int64 (or int32)
    const void*  jI       = d_in[4];                 // [M] int64 (or int32)
    float*       out      = (float*)d_out;           // [B, S, F] fp32

    dim3 tb(32, 8);

    k_detect<<<1, 1>>>((const long long*)iI);
    k_convert<<<Mdim / 256, 256>>>(iI, jI);

    k_transU<<<dim3(Fdim / 32, Ddim / 32), tb>>>(up_dec);   // U^T  [F, 768] fp32
    k_transX<<<dim3(Fdim / 32, BS / 32),   tb>>>(up_facts); // X^T  [F, 1024] fp16

    k_rowptr<<<(Fdim + 256) / 256, 256>>>();

    k_values<<<(Mdim * 32) / 256, 256>>>(down_enc);

    k_spmm<<<Fdim / SR, 256>>>(out);
}

// round 4
// speedup vs baseline: 1.4527x; 1.2921x over previous
#include <cuda_runtime.h>
#include <cuda_fp16.h>

#define Bdim 2
#define Sdim 512
#define Fdim 16384
#define Ddim 768
#define Mdim 262144
#define BS   (Bdim * Sdim)       // 1024
#define D4   (Ddim / 4)          // 192

// -------- device scratch (static, no allocation) --------
__device__ uint2  g_Uth[(size_t)Fdim * 192];    // up_decoder^T [F, 768] fp16, 24 MB
__device__ uint2  g_Xh[(size_t)Fdim * 256];     // up_facts^T   [F,1024] fp16, 32 MB
__device__ float  g_vals[Mdim];
__device__ int    g_ii[Mdim];
__device__ int    g_jj[Mdim];
__device__ int    g_rowptr[Fdim + 1];
__device__ int    g_is64;

// -------- dtype detection: int64 vs int32 indices --------
__global__ void k_detect(const long long* __restrict__ ip) {
    long long v = ip[65536];
    g_is64 = (v >= 0 && v < (long long)Fdim) ? 1 : 0;
}

__global__ void k_convert(const void* __restrict__ ip, const void* __restrict__ jp) {
    int m = blockIdx.x * blockDim.x + threadIdx.x;
    if (m >= Mdim) return;
    if (g_is64) {
        g_ii[m] = (int)((const long long*)ip)[m];
        g_jj[m] = (int)((const long long*)jp)[m];
    } else {
        g_ii[m] = ((const int*)ip)[m];
        g_jj[m] = ((const int*)jp)[m];
    }
}

// -------- CSR row pointers via binary search on sorted i --------
__global__ void k_rowptr() {
    int r = blockIdx.x * blockDim.x + threadIdx.x;
    if (r > Fdim) return;
    int lo = 0, hi = Mdim;
    while (lo < hi) {
        int mid = (lo + hi) >> 1;
        if (g_ii[mid] < r) lo = mid + 1; else hi = mid;
    }
    g_rowptr[r] = lo;
}

// -------- transpose U (fp32 -> fp16) --------
__global__ void k_transU(const float* __restrict__ src) {
    __shared__ float tile[32][33];
    int bx = blockIdx.x * 32, by = blockIdx.y * 32;
    int tx = threadIdx.x, ty0 = threadIdx.y;
#pragma unroll
    for (int ty = ty0; ty < 32; ty += 8)
        tile[ty][tx] = src[(size_t)(by + ty) * Fdim + (bx + tx)];
    __syncthreads();
    __half* dst = (__half*)g_Uth;
#pragma unroll
    for (int ty = ty0; ty < 32; ty += 8)
        dst[(size_t)(bx + ty) * Ddim + (by + tx)] = __float2half(tile[tx][ty]);
}

// -------- transpose X (fp32 -> fp16) --------
__global__ void k_transX(const float* __restrict__ src) {
    __shared__ float tile[32][33];
    int bx = blockIdx.x * 32, by = blockIdx.y * 32;
    int tx = threadIdx.x, ty0 = threadIdx.y;
#pragma unroll
    for (int ty = ty0; ty < 32; ty += 8)
        tile[ty][tx] = src[(size_t)(by + ty) * Fdim + (bx + tx)];
    __syncthreads();
    __half* dst = (__half*)g_Xh;
#pragma unroll
    for (int ty = ty0; ty < 32; ty += 8)
        dst[(size_t)(bx + ty) * BS + (by + tx)] = __float2half(tile[tx][ty]);
}

// -------- values: one block per row i. Dn[i] (fp32) cached in smem; each
// warp computes one connection's dot against Ut_h[j] (fp16). --------
__global__ void __launch_bounds__(128) k_values(const float* __restrict__ Dn) {
    __shared__ float4 sD[192];          // Dn[i] as 192 float4 (3 KB)
    int i    = blockIdx.x;
    int t    = threadIdx.x;
    int wid  = t >> 5, lane = t & 31;

    const float4* __restrict__ Dr = (const float4*)Dn + (size_t)i * D4;
    if (t < 192) sD[t] = Dr[t];
    if (t + 128 < 192) sD[t + 128] = Dr[t + 128];
    __syncthreads();

    int mb = g_rowptr[i], me = g_rowptr[i + 1];
    for (int m = mb + wid; m < me; m += 4) {
        int j = g_jj[m];
        const uint2* __restrict__ Ur = g_Uth + (size_t)j * 192;
        float s = 0.f;
#pragma unroll
        for (int k = 0; k < 6; k++) {
            int idx = k * 32 + lane;
            uint2  u = Ur[idx];
            float4 d = sD[idx];
            float2 lo = __half22float2(*(const __half2*)&u.x);
            float2 hi = __half22float2(*(const __half2*)&u.y);
            s += d.x * lo.x + d.y * lo.y + d.z * hi.x + d.w * hi.y;
        }
#pragma unroll
        for (int o = 16; o > 0; o >>= 1) s += __shfl_xor_sync(0xffffffffu, s, o);
        if (lane == 0) g_vals[m] = s;
    }
}

// -------- accumulate helper (function, not macro: no token-capture bugs) ----
__device__ __forceinline__ void acc_px(float4& a, float v, uint2 px) {
    float2 lo = __half22float2(*(const __half2*)&px.x);
    float2 hi = __half22float2(*(const __half2*)&px.y);
    a.x += v * lo.x; a.y += v * lo.y;
    a.z += v * hi.x; a.w += v * hi.y;
}

// -------- fused SpMM + output transpose, MLP-4 gather batches --------
#define SR 8
__global__ void __launch_bounds__(256) k_spmm(float* __restrict__ out) {
    __shared__ float stage[SR][1028];
    int t  = threadIdx.x;
    int r0 = blockIdx.x * SR;

#pragma unroll 1
    for (int rr = 0; rr < SR; rr++) {
        int r  = r0 + rr;
        int m  = g_rowptr[r], me = g_rowptr[r + 1];
        float4 a = make_float4(0.f, 0.f, 0.f, 0.f);

        // 4-wide batches: 4 independent L2 gathers in flight
        for (; m + 4 <= me; m += 4) {
            int   j0 = g_jj[m],     j1 = g_jj[m + 1];
            int   j2 = g_jj[m + 2], j3 = g_jj[m + 3];
            float v0 = g_vals[m],     v1 = g_vals[m + 1];
            float v2 = g_vals[m + 2], v3 = g_vals[m + 3];
            uint2 x0 = g_Xh[(size_t)j0 * 256 + t];
            uint2 x1 = g_Xh[(size_t)j1 * 256 + t];
            uint2 x2 = g_Xh[(size_t)j2 * 256 + t];
            uint2 x3 = g_Xh[(size_t)j3 * 256 + t];
            acc_px(a, v0, x0); acc_px(a, v1, x1);
            acc_px(a, v2, x2); acc_px(a, v3, x3);
        }
        for (; m < me; ++m) {
            int   j = g_jj[m];
            float v = g_vals[m];
            uint2 x = g_Xh[(size_t)j * 256 + t];
            acc_px(a, v, x);
        }
        *(float4*)&stage[rr][4 * t] = a;
    }
    __syncthreads();

#pragma unroll
    for (int it = 0; it < 8; it++) {
        int g  = it * 256 + t;
        int c  = g & 1;
        int bs = g >> 1;
        float4 o;
        o.x = stage[4 * c + 0][bs];
        o.y = stage[4 * c + 1][bs];
        o.z = stage[4 * c + 2][bs];
        o.w = stage[4 * c + 3][bs];
        *(float4*)&out[(size_t)bs * Fdim + r0 + 4 * c] = o;
    }
}

extern "C" void kernel_launch(void* const* d_in, const int* in_sizes, int n_in,
                              void* d_out, int out_size) {
    const float* up_facts = (const float*)d_in[0];   // [B, S, F] fp32
    const float* down_enc = (const float*)d_in[1];   // [F, D]    fp32
    const float* up_dec   = (const float*)d_in[2];   // [D, F]    fp32
    const void*  iI       = d_in[3];                 // [M] int64 (or int32)
    const void*  jI       = d_in[4];                 // [M] int64 (or int32)
    float*       out      = (float*)d_out;           // [B, S, F] fp32

    dim3 tb(32, 8);

    k_detect<<<1, 1>>>((const long long*)iI);
    k_convert<<<Mdim / 256, 256>>>(iI, jI);

    k_transU<<<dim3(Fdim / 32, Ddim / 32), tb>>>(up_dec);   // U^T fp16
    k_transX<<<dim3(Fdim / 32, BS / 32),   tb>>>(up_facts); // X^T fp16

    k_rowptr<<<(Fdim + 256) / 256, 256>>>();

    k_values<<<Fdim, 128>>>(down_enc);

    k_spmm<<<Fdim / SR, 256>>>(out);
}

// round 5
// speedup vs baseline: 1.6973x; 1.1683x over previous
#include <cuda_runtime.h>
#include <cuda_fp16.h>

#define Bdim 2
#define Sdim 512
#define Fdim 16384
#define Ddim 768
#define Mdim 262144
#define BS   (Bdim * Sdim)       // 1024
#define D4   (Ddim / 4)          // 192

// -------- device scratch (static, no allocation) --------
__device__ uint2  g_Uth[(size_t)Fdim * 192];    // up_decoder^T [F, 768] fp16, 24 MB
__device__ uint2  g_Xh[(size_t)Fdim * 256];     // up_facts^T   [F,1024] fp16, 32 MB
__device__ float  g_vals[Mdim];
__device__ int    g_ii[Mdim];
__device__ int    g_jj[Mdim];
__device__ int    g_rowptr[Fdim + 1];
__device__ int    g_is64;

// -------- dtype detection: int64 vs int32 indices --------
__global__ void k_detect(const long long* __restrict__ ip) {
    long long v = ip[65536];
    g_is64 = (v >= 0 && v < (long long)Fdim) ? 1 : 0;
}

__global__ void k_convert(const void* __restrict__ ip, const void* __restrict__ jp) {
    int m = blockIdx.x * blockDim.x + threadIdx.x;
    if (m >= Mdim) return;
    if (g_is64) {
        g_ii[m] = (int)((const long long*)ip)[m];
        g_jj[m] = (int)((const long long*)jp)[m];
    } else {
        g_ii[m] = ((const int*)ip)[m];
        g_jj[m] = ((const int*)jp)[m];
    }
}

// -------- CSR row pointers via binary search on sorted i --------
__global__ void k_rowptr() {
    int r = blockIdx.x * blockDim.x + threadIdx.x;
    if (r > Fdim) return;
    int lo = 0, hi = Mdim;
    while (lo < hi) {
        int mid = (lo + hi) >> 1;
        if (g_ii[mid] < r) lo = mid + 1; else hi = mid;
    }
    g_rowptr[r] = lo;
}

// -------- fused transpose + fp32->fp16, 64x64 tiles, half2-packed smem ----
// src: [nrows, F] fp32 (row dim = the dim that becomes contiguous halves in dst)
// dst: [F, nrows] fp16 viewed as uint rows of nrows/2.
// Load: thread grabs rows (2rp, 2rp+1) at col c -> pack half2 -> tile[c][rp]
//   (stride 33 => STS conflict-free; both gmem loads 128B/warp coalesced)
// Store: warp reads tile[f][lane] (stride-1, conflict-free), writes 128B row.
__device__ __forceinline__ void trans_h2_body(const float* __restrict__ src,
                                              uint* __restrict__ dst,
                                              int nrows) {
    __shared__ uint tile[64][33];
    int bx = blockIdx.x * 64;        // F offset
    int by = blockIdx.y * 64;        // row offset
    int t  = threadIdx.x;
    int c   = t & 63;
    int rp0 = t >> 6;                // 0..3
#pragma unroll
    for (int it = 0; it < 8; it++) {
        int rp = rp0 + it * 4;       // 0..31 row-pair
        int r  = by + 2 * rp;
        float a = src[(size_t)r * Fdim + bx + c];
        float b = src[(size_t)(r + 1) * Fdim + bx + c];
        __half2 h = __floats2half2_rn(a, b);
        tile[c][rp] = *(uint*)&h;
    }
    __syncthreads();
    int lane = t & 31;
    int f0   = t >> 5;               // 0..7
    int rowu = nrows >> 1;           // uints per dst row
#pragma unroll
    for (int it = 0; it < 8; it++) {
        int f = f0 + it * 8;
        dst[(size_t)(bx + f) * rowu + (by >> 1) + lane] = tile[f][lane];
    }
}

__global__ void __launch_bounds__(256) k_transU(const float* __restrict__ s) {
    trans_h2_body(s, (uint*)g_Uth, Ddim);
}
__global__ void __launch_bounds__(256) k_transX(const float* __restrict__ s) {
    trans_h2_body(s, (uint*)g_Xh, BS);
}

// -------- values: one block per row i. Dn[i] (fp32) cached in smem; each
// warp computes one connection's dot against Ut_h[j] (fp16). --------
__global__ void __launch_bounds__(128) k_values(const float* __restrict__ Dn) {
    __shared__ float4 sD[192];          // Dn[i] as 192 float4 (3 KB)
    int i    = blockIdx.x;
    int t    = threadIdx.x;
    int wid  = t >> 5, lane = t & 31;

    const float4* __restrict__ Dr = (const float4*)Dn + (size_t)i * D4;
    if (t < 192) sD[t] = Dr[t];
    if (t + 128 < 192) sD[t + 128] = Dr[t + 128];
    __syncthreads();

    int mb = g_rowptr[i], me = g_rowptr[i + 1];
    for (int m = mb + wid; m < me; m += 4) {
        int j = g_jj[m];
        const uint2* __restrict__ Ur = g_Uth + (size_t)j * 192;
        float s = 0.f;
#pragma unroll
        for (int k = 0; k < 6; k++) {
            int idx = k * 32 + lane;
            uint2  u = Ur[idx];
            float4 d = sD[idx];
            float2 lo = __half22float2(*(const __half2*)&u.x);
            float2 hi = __half22float2(*(const __half2*)&u.y);
            s += d.x * lo.x + d.y * lo.y + d.z * hi.x + d.w * hi.y;
        }
#pragma unroll
        for (int o = 16; o > 0; o >>= 1) s += __shfl_xor_sync(0xffffffffu, s, o);
        if (lane == 0) g_vals[m] = s;
    }
}

// -------- accumulate helper (function, not macro) ----
__device__ __forceinline__ void acc_px(float4& a, float v, uint2 px) {
    float2 lo = __half22float2(*(const __half2*)&px.x);
    float2 hi = __half22float2(*(const __half2*)&px.y);
    a.x += v * lo.x; a.y += v * lo.y;
    a.z += v * hi.x; a.w += v * hi.y;
}

// -------- fused SpMM + output transpose, MLP-4 gather batches --------
#define SR 8
__global__ void __launch_bounds__(256) k_spmm(float* __restrict__ out) {
    __shared__ float stage[SR][1028];
    int t  = threadIdx.x;
    int r0 = blockIdx.x * SR;

#pragma unroll 1
    for (int rr = 0; rr < SR; rr++) {
        int r  = r0 + rr;
        int m  = g_rowptr[r], me = g_rowptr[r + 1];
        float4 a = make_float4(0.f, 0.f, 0.f, 0.f);

        for (; m + 4 <= me; m += 4) {
            int   j0 = g_jj[m],     j1 = g_jj[m + 1];
            int   j2 = g_jj[m + 2], j3 = g_jj[m + 3];
            float v0 = g_vals[m],     v1 = g_vals[m + 1];
            float v2 = g_vals[m + 2], v3 = g_vals[m + 3];
            uint2 x0 = g_Xh[(size_t)j0 * 256 + t];
            uint2 x1 = g_Xh[(size_t)j1 * 256 + t];
            uint2 x2 = g_Xh[(size_t)j2 * 256 + t];
            uint2 x3 = g_Xh[(size_t)j3 * 256 + t];
            acc_px(a, v0, x0); acc_px(a, v1, x1);
            acc_px(a, v2, x2); acc_px(a, v3, x3);
        }
        for (; m < me; ++m) {
            int   j = g_jj[m];
            float v = g_vals[m];
            uint2 x = g_Xh[(size_t)j * 256 + t];
            acc_px(a, v, x);
        }
        *(float4*)&stage[rr][4 * t] = a;
    }
    __syncthreads();

#pragma unroll
    for (int it = 0; it < 8; it++) {
        int g  = it * 256 + t;
        int c  = g & 1;
        int bs = g >> 1;
        float4 o;
        o.x = stage[4 * c + 0][bs];
        o.y = stage[4 * c + 1][bs];
        o.z = stage[4 * c + 2][bs];
        o.w = stage[4 * c + 3][bs];
        *(float4*)&out[(size_t)bs * Fdim + r0 + 4 * c] = o;
    }
}

extern "C" void kernel_launch(void* const* d_in, const int* in_sizes, int n_in,
                              void* d_out, int out_size) {
    const float* up_facts = (const float*)d_in[0];   // [B, S, F] fp32
    const float* down_enc = (const float*)d_in[1];   // [F, D]    fp32
    const float* up_dec   = (const float*)d_in[2];   // [D, F]    fp32
    const void*  iI       = d_in[3];                 // [M] int64 (or int32)
    const void*  jI       = d_in[4];                 // [M] int64 (or int32)
    float*       out      = (float*)d_out;           // [B, S, F] fp32

    k_detect<<<1, 1>>>((const long long*)iI);
    k_convert<<<Mdim / 256, 256>>>(iI, jI);

    k_transU<<<dim3(Fdim / 64, Ddim / 64), 256>>>(up_dec);   // U^T fp16
    k_transX<<<dim3(Fdim / 64, BS / 64),   256>>>(up_facts); // X^T fp16

    k_rowptr<<<(Fdim + 256) / 256, 256>>>();

    k_values<<<Fdim, 128>>>(down_enc);

    k_spmm<<<Fdim / SR, 256>>>(out);
}